// round 2
// baseline (speedup 1.0000x reference)
#include <cuda_runtime.h>

// Problem constants (SLEN=208, PTILE=8, STEP=2, EDGE=3, MAXDET=2)
#define BATCH 16
#define NSRC  100
#define NSRC_TOT (BATCH * NSRC)   // 1600
#define NFLUX 5
#define NT    101                 // tiles per dim
#define PT    (NT * NT)           // 10201
#define BP    (BATCH * PT)        // 163216
// Output sections (float32, concatenated):
//   n [BP] | locs [BP*4] | fluxes [BP*10] | is_on [BP*2]
#define OFF_L (BP)
#define OFF_F (OFF_L + BP * 4)
#define OFF_I (OFF_F + BP * 10)
#define OUT_FLOATS (OFF_I + BP * 2)          // 2,774,672 (divisible by 4)
#define N4 (OUT_FLOATS / 4)                  // 693,668 float4

#define GRID 148
#define TPB  256
#define CHUNK4 ((N4 + GRID - 1) / GRID)      // 4688

__global__ __launch_bounds__(TPB, 1)
void fused_kernel(const float* __restrict__ locs,
                  const float* __restrict__ fluxes,
                  float* __restrict__ out) {
    __shared__ int stile[NSRC_TOT];

    const int t  = threadIdx.x;
    const int c0 = blockIdx.x * CHUNK4;
    const int c1 = min(c0 + CHUNK4, N4);

    // ---- Phase A: zero-fill my chunk (float4, fully coalesced) ----
    float4* __restrict__ o4 = (float4*)out;
    const float4 z = make_float4(0.f, 0.f, 0.f, 0.f);
    for (int i = c0 + t; i < c1; i += TPB) o4[i] = z;

    // ---- Phase B: map all 1600 sources -> tile id (or -1) into shared ----
    for (int idx = t; idx < NSRC_TOT; idx += TPB) {
        float p0 = __ldg(&locs[idx * 2 + 0]) * 207.0f;   // SLEN-1
        float p1 = __ldg(&locs[idx * 2 + 1]) * 207.0f;
        int kx = (int)floorf((p0 - 2.5f) * 0.5f);
        int ky = (int)floorf((p1 - 2.5f) * 0.5f);
        float lx = 2.0f * (float)kx + 2.5f;              // exact in fp32
        float ly = 2.0f * (float)ky + 2.5f;
        bool v0 = (kx >= 0) && (kx < NT) && (p0 > lx) && (p0 < lx + 2.0f) && (p0 != 0.0f);
        bool v1 = (ky >= 0) && (ky < NT) && (p1 > ly) && (p1 < ly + 2.0f) && (p1 != 0.0f);
        stile[idx] = (v0 && v1) ? (kx * NT + ky) : -1;
    }
    __syncthreads();   // orders phase-A global stores before phase-C stores (cta scope)

    // ---- Phase C: scatter writes that land in MY byte range ----
    const int lo = c0 * 4;          // float-index range owned by this block
    const int hi = c1 * 4;

    for (int idx = t; idx < NSRC_TOT; idx += TPB) {
        const int tile = stile[idx];
        if (tile < 0) continue;
        const int b = idx / NSRC;
        const int s = idx - b * NSRC;
        const int g = b * PT + tile;

        // Does any of this cell's 4 spans overlap [lo, hi)?
        const int aN = g;
        const int aL = OFF_L + 4 * g;
        const int aF = OFF_F + 10 * g;
        const int aI = OFF_I + 2 * g;
        bool any = (aN >= lo && aN < hi)
                || (aL < hi && aL + 4  > lo)
                || (aF < hi && aF + 10 > lo)
                || (aI < hi && aI + 2  > lo);
        if (!any) continue;

        // Rank/count among same-tile sources in this batch (stable-sort order)
        const int base = b * NSRC;
        int count = 0, rank = 0;
        #pragma unroll 4
        for (int j = 0; j < NSRC; j++) {
            if (stile[base + j] == tile) { count++; if (j < s) rank++; }
        }

        if (rank == 0 && aN >= lo && aN < hi)
            out[aN] = (float)(count < 2 ? count : 2);

        if (rank < 2) {
            // recompute normalized locs (inputs are L2-hot)
            float p0 = __ldg(&locs[idx * 2 + 0]) * 207.0f;
            float p1 = __ldg(&locs[idx * 2 + 1]) * 207.0f;
            int kx = tile / NT, ky = tile - kx * NT;
            float fx = (p0 - (2.0f * (float)kx + 2.5f)) * 0.5f;
            float fy = (p1 - (2.0f * (float)ky + 2.5f)) * 0.5f;

            int a = aL + 2 * rank;
            if (a     >= lo && a     < hi) out[a]     = fx;
            if (a + 1 >= lo && a + 1 < hi) out[a + 1] = fy;

            const float* fl = fluxes + idx * NFLUX;
            #pragma unroll
            for (int j = 0; j < NFLUX; j++) {
                int af = aF + 5 * rank + j;
                if (af >= lo && af < hi) out[af] = __ldg(&fl[j]);
            }

            int ai = aI + rank;
            if (ai >= lo && ai < hi) out[ai] = 1.0f;
        }
    }
}

extern "C" void kernel_launch(void* const* d_in, const int* in_sizes, int n_in,
                              void* d_out, int out_size) {
    const float* locs   = (const float*)d_in[0];   // (16, 100, 2) f32
    const float* fluxes = (const float*)d_in[1];   // (16, 100, 5) f32
    fused_kernel<<<GRID, TPB>>>(locs, fluxes, (float*)d_out);
}

// round 3
// speedup vs baseline: 1.1386x; 1.1386x over previous
#include <cuda_runtime.h>

// Problem constants (SLEN=208, PTILE=8, STEP=2, EDGE=3, MAXDET=2)
#define BATCH 16
#define NSRC  100
#define NSRC_TOT (BATCH * NSRC)   // 1600
#define NFLUX 5
#define NT    101                 // tiles per dim
#define PT    (NT * NT)           // 10201
#define BP    (BATCH * PT)        // 163216
// Output sections (float32, concatenated):
//   n [BP] | locs [BP*4] | fluxes [BP*10] | is_on [BP*2]
#define OFF_L (BP)                 // 163216
#define OFF_F (OFF_L + BP * 4)     // 816080
#define OFF_I (OFF_F + BP * 10)    // 2448240

#define GRID  148
#define TPB   256
#define CHUNK ((BP + GRID - 1) / GRID)   // 1103 cells per block

// Zero floats [a, b) with float4 body + scalar head/tail. Cooperative over TPB threads.
__device__ __forceinline__ void zero_range(float* __restrict__ out, int a, int b, int t) {
    int a4 = (a + 3) & ~3;
    if (a4 > b) a4 = b;
    int b4 = b & ~3;
    if (b4 < a4) b4 = a4;
    if (a + t < a4) out[a + t] = 0.f;                        // head (<4)
    float4 z = make_float4(0.f, 0.f, 0.f, 0.f);
    float4* __restrict__ o4 = (float4*)out;
    for (int i = (a4 >> 2) + t; i < (b4 >> 2); i += TPB) o4[i] = z;
    if (b4 + t < b) out[b4 + t] = 0.f;                       // tail (<4)
}

// Map one source's pixel coords to (tile, fx, fy); returns tile or -1.
// Bit-identical to the verified R1 formulation.
__device__ __forceinline__ int map_source(float l0, float l1, float& fx, float& fy) {
    float p0 = l0 * 207.0f;                                  // SLEN-1
    float p1 = l1 * 207.0f;
    int kx = (int)floorf((p0 - 2.5f) * 0.5f);
    int ky = (int)floorf((p1 - 2.5f) * 0.5f);
    float lx = 2.0f * (float)kx + 2.5f;                      // exact fp32
    float ly = 2.0f * (float)ky + 2.5f;
    bool v0 = (kx >= 0) && (kx < NT) && (p0 > lx) && (p0 < lx + 2.0f) && (p0 != 0.0f);
    bool v1 = (ky >= 0) && (ky < NT) && (p1 > ly) && (p1 < ly + 2.0f) && (p1 != 0.0f);
    if (!(v0 && v1)) return -1;
    fx = (p0 - lx) * 0.5f;                                   // (lp - left) / scale, exact
    fy = (p1 - ly) * 0.5f;
    return kx * NT + ky;
}

__global__ __launch_bounds__(TPB, 1)
void fused_kernel(const float* __restrict__ locs,
                  const float* __restrict__ fluxes,
                  float* __restrict__ out) {
    __shared__ int s_cnt;
    __shared__ int s_ent[NSRC_TOT];   // (g << 11) | idx  (g < 2^18, idx < 2^11)

    const int t  = threadIdx.x;
    const int g0 = blockIdx.x * CHUNK;
    const int g1 = min(g0 + CHUNK, BP);

    if (t == 0) s_cnt = 0;
    __syncthreads();

    // ---- Phase A: zero-fill my 4 per-section slices (coalesced) ----
    zero_range(out, g0,                g1,                t);
    zero_range(out, OFF_L + 4 * g0,    OFF_L + 4 * g1,    t);
    zero_range(out, OFF_F + 10 * g0,   OFF_F + 10 * g1,   t);
    zero_range(out, OFF_I + 2 * g0,    OFF_I + 2 * g1,    t);

    // ---- Phase B: scan all sources once, keep the ones in my g-range ----
    const float2* __restrict__ l2 = (const float2*)locs;
    for (int idx = t; idx < NSRC_TOT; idx += TPB) {
        float2 l = __ldg(&l2[idx]);
        float fx, fy;
        int tile = map_source(l.x, l.y, fx, fy);
        if (tile < 0) continue;
        int b = idx / NSRC;             // idx = b*NSRC + s
        int g = b * PT + tile;
        if (g >= g0 && g < g1) {
            int pos = atomicAdd(&s_cnt, 1);
            s_ent[pos] = (g << 11) | idx;
        }
    }
    __syncthreads();   // orders Phase-A stores before Phase-C stores (CTA scope)

    // ---- Phase C: rank within the tiny local list, write cell payloads ----
    const int cnt = s_cnt;
    for (int e = t; e < cnt; e += TPB) {
        const int ent  = s_ent[e];
        const int g    = ent >> 11;
        const int idx  = ent & 2047;

        int count = 0, rank = 0;
        for (int j = 0; j < cnt; j++) {
            int o = s_ent[j];
            if ((o >> 11) == g) {
                count++;
                if ((o & 2047) < idx) rank++;
            }
        }

        if (rank == 0)
            out[g] = (float)(count < 2 ? count : 2);   // min(n, MAXDET)

        if (rank < 2) {
            float2 l = __ldg(&l2[idx]);
            float fx, fy;
            (void)map_source(l.x, l.y, fx, fy);        // recompute, identical math
            *(float2*)(out + OFF_L + 4 * g + 2 * rank) = make_float2(fx, fy);

            const float* __restrict__ fl = fluxes + idx * NFLUX;
            int fb = OFF_F + 10 * g + 5 * rank;
            #pragma unroll
            for (int j = 0; j < NFLUX; j++) out[fb + j] = __ldg(&fl[j]);

            out[OFF_I + 2 * g + rank] = 1.0f;
        }
    }
}

extern "C" void kernel_launch(void* const* d_in, const int* in_sizes, int n_in,
                              void* d_out, int out_size) {
    const float* locs   = (const float*)d_in[0];   // (16, 100, 2) f32
    const float* fluxes = (const float*)d_in[1];   // (16, 100, 5) f32
    fused_kernel<<<GRID, TPB>>>(locs, fluxes, (float*)d_out);
}

// round 4
// speedup vs baseline: 1.2731x; 1.1181x over previous
#include <cuda_runtime.h>

// Problem constants (SLEN=208, PTILE=8, STEP=2, EDGE=3, MAXDET=2)
#define BATCH 16
#define NSRC  100
#define NFLUX 5
#define NT    101                 // tiles per dim
#define PT    (NT * NT)           // 10201
#define BP    (BATCH * PT)        // 163216
// Output sections (float32, concatenated):
//   n [BP] | locs [BP*4] | fluxes [BP*10] | is_on [BP*2]
#define OFF_L (BP)                 // 163216
#define OFF_F (OFF_L + BP * 4)     // 816080
#define OFF_I (OFF_F + BP * 10)    // 2448240

#define TPB    256
#define CHUNK  138                         // cells per block (< PT: spans <= 2 batches)
#define GRID   ((BP + CHUNK - 1) / CHUNK)  // 1183
#define MAXLOC 256                         // >= 2*NSRC worst-case in-range sources

// Zero floats [a, b): float4 body + scalar head/tail, cooperative over TPB threads.
__device__ __forceinline__ void zero_range(float* __restrict__ out, int a, int b, int t) {
    int a4 = (a + 3) & ~3;
    if (a4 > b) a4 = b;
    int b4 = b & ~3;
    if (b4 < a4) b4 = a4;
    if (a + t < a4) out[a + t] = 0.f;                        // head (<4)
    float4 z = make_float4(0.f, 0.f, 0.f, 0.f);
    float4* __restrict__ o4 = (float4*)out;
    for (int i = (a4 >> 2) + t; i < (b4 >> 2); i += TPB) o4[i] = z;
    if (b4 + t < b) out[b4 + t] = 0.f;                       // tail (<4)
}

// Map pixel coords -> (tile, fx, fy); returns tile or -1. Bit-identical to R1.
__device__ __forceinline__ int map_source(float l0, float l1, float& fx, float& fy) {
    float p0 = l0 * 207.0f;                                  // SLEN-1
    float p1 = l1 * 207.0f;
    int kx = (int)floorf((p0 - 2.5f) * 0.5f);
    int ky = (int)floorf((p1 - 2.5f) * 0.5f);
    float lx = 2.0f * (float)kx + 2.5f;                      // exact fp32
    float ly = 2.0f * (float)ky + 2.5f;
    bool v0 = (kx >= 0) && (kx < NT) && (p0 > lx) && (p0 < lx + 2.0f) && (p0 != 0.0f);
    bool v1 = (ky >= 0) && (ky < NT) && (p1 > ly) && (p1 < ly + 2.0f) && (p1 != 0.0f);
    if (!(v0 && v1)) return -1;
    fx = (p0 - lx) * 0.5f;                                   // (lp - left)/scale, exact
    fy = (p1 - ly) * 0.5f;
    return kx * NT + ky;
}

__global__ __launch_bounds__(TPB)
void fused_kernel(const float* __restrict__ locs,
                  const float* __restrict__ fluxes,
                  float* __restrict__ out) {
    __shared__ int   s_cnt;
    __shared__ int   s_ent[MAXLOC];   // (g << 11) | idx
    __shared__ float s_fx[MAXLOC];
    __shared__ float s_fy[MAXLOC];

    const int t  = threadIdx.x;
    const int g0 = blockIdx.x * CHUNK;
    if (g0 >= BP) return;
    const int g1 = min(g0 + CHUNK, BP);

    if (t == 0) s_cnt = 0;
    __syncthreads();

    // ---- Phase A: zero my 4 per-section slices (~2.3 float4/thread total) ----
    zero_range(out, g0,              g1,              t);
    zero_range(out, OFF_L + 4 * g0,  OFF_L + 4 * g1,  t);
    zero_range(out, OFF_F + 10 * g0, OFF_F + 10 * g1, t);
    zero_range(out, OFF_I + 2 * g0,  OFF_I + 2 * g1,  t);

    // ---- Phase B: only batches overlapping my cell range can contribute ----
    const int b_lo = g0 / PT;
    const int b_hi = (g1 - 1) / PT;           // b_hi - b_lo <= 1 since CHUNK < PT
    const int i_lo = b_lo * NSRC;
    const int i_hi = (b_hi + 1) * NSRC;       // <= i_lo + 200

    const float2* __restrict__ l2 = (const float2*)locs;
    for (int idx = i_lo + t; idx < i_hi; idx += TPB) {   // <= 1 trip
        float2 l = __ldg(&l2[idx]);
        float fx, fy;
        int tile = map_source(l.x, l.y, fx, fy);
        if (tile < 0) continue;
        int g = (idx / NSRC) * PT + tile;
        if (g >= g0 && g < g1) {
            int pos = atomicAdd(&s_cnt, 1);
            s_ent[pos] = (g << 11) | idx;
            s_fx[pos]  = fx;
            s_fy[pos]  = fy;
        }
    }
    __syncthreads();   // orders Phase-A stores before Phase-C stores (CTA scope)

    // ---- Phase C: rank within tiny local list (~1-3 entries), write payloads ----
    const int cnt = s_cnt;
    for (int e = t; e < cnt; e += TPB) {
        const int ent = s_ent[e];
        const int g   = ent >> 11;
        const int idx = ent & 2047;

        int count = 0, rank = 0;
        for (int j = 0; j < cnt; j++) {
            int o = s_ent[j];
            if ((o >> 11) == g) {
                count++;
                if ((o & 2047) < idx) rank++;
            }
        }

        if (rank == 0)
            out[g] = (float)(count < 2 ? count : 2);     // min(n, MAXDET)

        if (rank < 2) {
            *(float2*)(out + OFF_L + 4 * g + 2 * rank) = make_float2(s_fx[e], s_fy[e]);

            const float* __restrict__ fl = fluxes + idx * NFLUX;
            int fb = OFF_F + 10 * g + 5 * rank;
            #pragma unroll
            for (int j = 0; j < NFLUX; j++) out[fb + j] = __ldg(&fl[j]);

            out[OFF_I + 2 * g + rank] = 1.0f;
        }
    }
}

extern "C" void kernel_launch(void* const* d_in, const int* in_sizes, int n_in,
                              void* d_out, int out_size) {
    const float* locs   = (const float*)d_in[0];   // (16, 100, 2) f32
    const float* fluxes = (const float*)d_in[1];   // (16, 100, 5) f32
    fused_kernel<<<GRID, TPB>>>(locs, fluxes, (float*)d_out);
}